// round 2
// baseline (speedup 1.0000x reference)
#include <cuda_runtime.h>
#include <math.h>

#define S_LEN 2048
#define EMB   1024
#define NH    16
#define HD    64
#define BATCH 2
#define MTOT  (BATCH*S_LEN)   // 4096

// Scratch (device globals: allocation-free)
__device__ float g_q[BATCH*NH*S_LEN*HD];
__device__ float g_k[BATCH*NH*S_LEN*HD];
__device__ float g_v[BATCH*NH*S_LEN*HD];
__device__ float g_attn[MTOT*EMB];

// ---------------------------------------------------------------------------
// SGEMM: C = A @ W^T + bias.  A:[M,EMB] row-major, W:[N,EMB] row-major.
// M=4096, N=EMB=1024, K=EMB=1024 fixed.
// mode 0: C[m*EMB+n] plain.  mode 1: scatter to [B,H,S,D] (QKV head split).
// ---------------------------------------------------------------------------
#define BM 128
#define BN 128
#define BKS 16

__device__ __forceinline__
void gemm_body(const float* __restrict__ A, const float* __restrict__ W,
               const float* __restrict__ bias, float* __restrict__ C, int mode)
{
    __shared__ float As[BKS][BM+4];
    __shared__ float Bs[BKS][BN+4];
    const int tid = threadIdx.x;
    const int m0 = blockIdx.y * BM;
    const int n0 = blockIdx.x * BN;
    const int lr = tid >> 2;          // 0..63
    const int lc = (tid & 3) << 2;    // 0,4,8,12
    const int tr = (tid >> 4) << 3;   // 0..120 step 8
    const int tc = (tid & 15) << 3;

    float acc[8][8];
    #pragma unroll
    for (int i = 0; i < 8; i++)
        #pragma unroll
        for (int j = 0; j < 8; j++) acc[i][j] = 0.0f;

    const float* Aptr = A + (size_t)(m0 + lr) * EMB + lc;
    const float* Wptr = W + (size_t)(n0 + lr) * EMB + lc;

    for (int k0 = 0; k0 < EMB; k0 += BKS) {
        float4 a0 = *(const float4*)(Aptr + k0);
        float4 a1 = *(const float4*)(Aptr + 64 * EMB + k0);
        float4 b0 = *(const float4*)(Wptr + k0);
        float4 b1 = *(const float4*)(Wptr + 64 * EMB + k0);
        __syncthreads();
        As[lc+0][lr] = a0.x; As[lc+1][lr] = a0.y; As[lc+2][lr] = a0.z; As[lc+3][lr] = a0.w;
        As[lc+0][lr+64] = a1.x; As[lc+1][lr+64] = a1.y; As[lc+2][lr+64] = a1.z; As[lc+3][lr+64] = a1.w;
        Bs[lc+0][lr] = b0.x; Bs[lc+1][lr] = b0.y; Bs[lc+2][lr] = b0.z; Bs[lc+3][lr] = b0.w;
        Bs[lc+0][lr+64] = b1.x; Bs[lc+1][lr+64] = b1.y; Bs[lc+2][lr+64] = b1.z; Bs[lc+3][lr+64] = b1.w;
        __syncthreads();
        #pragma unroll
        for (int k = 0; k < BKS; k++) {
            float a[8], b[8];
            *(float4*)&a[0] = *(const float4*)&As[k][tr];
            *(float4*)&a[4] = *(const float4*)&As[k][tr+4];
            *(float4*)&b[0] = *(const float4*)&Bs[k][tc];
            *(float4*)&b[4] = *(const float4*)&Bs[k][tc+4];
            #pragma unroll
            for (int i = 0; i < 8; i++)
                #pragma unroll
                for (int j = 0; j < 8; j++)
                    acc[i][j] = fmaf(a[i], b[j], acc[i][j]);
        }
    }

    #pragma unroll
    for (int i = 0; i < 8; i++) {
        int m = m0 + tr + i;
        #pragma unroll
        for (int j = 0; j < 8; j++) {
            int n = n0 + tc + j;
            float val = acc[i][j] + bias[n];
            if (mode == 0) {
                C[(size_t)m * EMB + n] = val;
            } else {
                int b_ = m >> 11;       // m / 2048
                int s_ = m & 2047;
                int h_ = n >> 6;        // n / 64
                int d_ = n & 63;
                C[(((size_t)(b_ * NH + h_) * S_LEN) + s_) * HD + d_] = val;
            }
        }
    }
}

// Fused QKV: blockIdx.z picks {Q,K,V} weight/bias/output.
__global__ __launch_bounds__(256)
void qkv_gemm_kernel(const float* __restrict__ x,
                     const float* __restrict__ wq, const float* __restrict__ bq,
                     const float* __restrict__ wk, const float* __restrict__ bk,
                     const float* __restrict__ wv, const float* __restrict__ bv,
                     float* __restrict__ qp, float* __restrict__ kp, float* __restrict__ vp)
{
    const float* W;
    const float* B;
    float* C;
    if (blockIdx.z == 0)      { W = wq; B = bq; C = qp; }
    else if (blockIdx.z == 1) { W = wk; B = bk; C = kp; }
    else                      { W = wv; B = bv; C = vp; }
    gemm_body(x, W, B, C, 1);
}

__global__ __launch_bounds__(256)
void out_gemm_kernel(const float* __restrict__ A, const float* __restrict__ W,
                     const float* __restrict__ bias, float* __restrict__ C)
{
    gemm_body(A, W, bias, C, 0);
}

// ---------------------------------------------------------------------------
// Flash attention (fp32): one CTA per (bh, 64-row Q tile); Bc=64, online softmax.
// Thread (ty,tx) owns rows {ty+16i}, cols {tx+16j} of 64x64 tiles.
// Reduction dims vectorized with float4 (V stored transposed in smem).
// ---------------------------------------------------------------------------
#define FTS 68   // padded smem row stride (floats)

__global__ __launch_bounds__(256)
void flash_kernel()
{
    extern __shared__ float sm[];
    float* Qs = sm;                 // 64*FTS
    float* Ks = Qs + 64 * FTS;
    float* Vt = Ks + 64 * FTS;      // transposed: Vt[d][t]
    float* Ps = Vt + 64 * FTS;

    const int tid = threadIdx.x;
    const int ty = tid >> 4;
    const int tx = tid & 15;
    const int qt = blockIdx.x;      // 0..31 query tiles
    const int bh = blockIdx.y;      // 0..31 (b*NH + h)

    const float* Q = g_q + ((size_t)bh * S_LEN + qt * 64) * HD;
    const float* K = g_k + (size_t)bh * S_LEN * HD;
    const float* V = g_v + (size_t)bh * S_LEN * HD;

    // Load Q tile once
    #pragma unroll
    for (int u = 0; u < 4; u++) {
        int f = tid + 256 * u;      // float4 index, 0..1023
        int row = f >> 4;
        int c4 = f & 15;
        float4 v4 = *(const float4*)(Q + row * HD + c4 * 4);
        *(float4*)&Qs[row * FTS + c4 * 4] = v4;
    }

    float m_i[4], l_i[4], acc[4][4];
    #pragma unroll
    for (int i = 0; i < 4; i++) {
        m_i[i] = -1e30f; l_i[i] = 0.0f;
        #pragma unroll
        for (int j = 0; j < 4; j++) acc[i][j] = 0.0f;
    }

    for (int kt = 0; kt < S_LEN / 64; kt++) {
        __syncthreads();   // previous iter done reading Ks/Vt/Ps
        const float* Kp = K + kt * 64 * HD;
        const float* Vp = V + kt * 64 * HD;
        #pragma unroll
        for (int u = 0; u < 4; u++) {
            int f = tid + 256 * u;
            int row = f >> 4;
            int c4 = f & 15;
            float4 kv = *(const float4*)(Kp + row * HD + c4 * 4);
            *(float4*)&Ks[row * FTS + c4 * 4] = kv;
            float4 vv = *(const float4*)(Vp + row * HD + c4 * 4);
            Vt[(c4*4+0) * FTS + row] = vv.x;
            Vt[(c4*4+1) * FTS + row] = vv.y;
            Vt[(c4*4+2) * FTS + row] = vv.z;
            Vt[(c4*4+3) * FTS + row] = vv.w;
        }
        __syncthreads();

        // S = Q @ K^T * 0.125
        float s[4][4];
        #pragma unroll
        for (int i = 0; i < 4; i++)
            #pragma unroll
            for (int j = 0; j < 4; j++) s[i][j] = 0.0f;
        #pragma unroll
        for (int d4 = 0; d4 < 16; d4++) {
            float4 qv[4], kv[4];
            #pragma unroll
            for (int i = 0; i < 4; i++) qv[i] = *(const float4*)&Qs[(ty + 16*i) * FTS + d4 * 4];
            #pragma unroll
            for (int j = 0; j < 4; j++) kv[j] = *(const float4*)&Ks[(tx + 16*j) * FTS + d4 * 4];
            #pragma unroll
            for (int i = 0; i < 4; i++)
                #pragma unroll
                for (int j = 0; j < 4; j++)
                    s[i][j] += qv[i].x*kv[j].x + qv[i].y*kv[j].y + qv[i].z*kv[j].z + qv[i].w*kv[j].w;
        }

        // online softmax per row
        #pragma unroll
        for (int i = 0; i < 4; i++) {
            float rm = -1e30f;
            #pragma unroll
            for (int j = 0; j < 4; j++) { s[i][j] *= 0.125f; rm = fmaxf(rm, s[i][j]); }
            #pragma unroll
            for (int off = 1; off < 16; off <<= 1)
                rm = fmaxf(rm, __shfl_xor_sync(0xffffffffu, rm, off));
            float mnew = fmaxf(m_i[i], rm);
            float scale = __expf(m_i[i] - mnew);
            float rs = 0.0f;
            #pragma unroll
            for (int j = 0; j < 4; j++) {
                float p = __expf(s[i][j] - mnew);
                s[i][j] = p;
                rs += p;
            }
            #pragma unroll
            for (int off = 1; off < 16; off <<= 1)
                rs += __shfl_xor_sync(0xffffffffu, rs, off);
            l_i[i] = l_i[i] * scale + rs;
            m_i[i] = mnew;
            #pragma unroll
            for (int j = 0; j < 4; j++) acc[i][j] *= scale;
            #pragma unroll
            for (int j = 0; j < 4; j++)
                Ps[(ty + 16*i) * FTS + tx + 16*j] = s[i][j];
        }
        __syncthreads();

        // O += P @ V  (Vt[d][t], dot over t, float4)
        #pragma unroll
        for (int t4 = 0; t4 < 16; t4++) {
            float4 pv[4], vv[4];
            #pragma unroll
            for (int i = 0; i < 4; i++) pv[i] = *(const float4*)&Ps[(ty + 16*i) * FTS + t4 * 4];
            #pragma unroll
            for (int j = 0; j < 4; j++) vv[j] = *(const float4*)&Vt[(tx + 16*j) * FTS + t4 * 4];
            #pragma unroll
            for (int i = 0; i < 4; i++)
                #pragma unroll
                for (int j = 0; j < 4; j++)
                    acc[i][j] += pv[i].x*vv[j].x + pv[i].y*vv[j].y + pv[i].z*vv[j].z + pv[i].w*vv[j].w;
        }
    }

    // normalize + write to [B,S,E]
    const int b_ = bh >> 4;
    const int h_ = bh & 15;
    #pragma unroll
    for (int i = 0; i < 4; i++) {
        int srow = qt * 64 + ty + 16 * i;
        float inv = 1.0f / l_i[i];
        #pragma unroll
        for (int j = 0; j < 4; j++)
            g_attn[((size_t)(b_ * S_LEN + srow)) * EMB + h_ * HD + tx + 16 * j] = acc[i][j] * inv;
    }
}

extern "C" void kernel_launch(void* const* d_in, const int* in_sizes, int n_in,
                              void* d_out, int out_size)
{
    const float* x  = (const float*)d_in[0];
    const float* wq = (const float*)d_in[1];
    const float* bq = (const float*)d_in[2];
    const float* wk = (const float*)d_in[3];
    const float* bk = (const float*)d_in[4];
    const float* wv = (const float*)d_in[5];
    const float* bv = (const float*)d_in[6];
    const float* wo = (const float*)d_in[7];
    const float* bo = (const float*)d_in[8];
    float* out = (float*)d_out;

    float *qp, *kp, *vp, *ap;
    cudaGetSymbolAddress((void**)&qp, g_q);
    cudaGetSymbolAddress((void**)&kp, g_k);
    cudaGetSymbolAddress((void**)&vp, g_v);
    cudaGetSymbolAddress((void**)&ap, g_attn);

    dim3 gq(EMB / BN, MTOT / BM, 3);   // 8 x 32 x 3
    qkv_gemm_kernel<<<gq, 256>>>(x, wq, bq, wk, bk, wv, bv, qp, kp, vp);

    int smem = 4 * 64 * FTS * sizeof(float);   // 69632 B
    static int smem_set = 0;
    if (!smem_set) {
        cudaFuncSetAttribute(flash_kernel, cudaFuncAttributeMaxDynamicSharedMemorySize, smem);
        smem_set = 1;
    }
    flash_kernel<<<dim3(32, 32), 256, smem>>>();

    dim3 gg(EMB / BN, MTOT / BM);      // 8 x 32
    out_gemm_kernel<<<gg, 256>>>(ap, wo, bo, out);
}

// round 4
// speedup vs baseline: 6.3335x; 6.3335x over previous
#include <cuda_runtime.h>
#include <cuda_fp16.h>
#include <cstdint>

#define S_LEN 2048
#define EMB   1024
#define NH    16
#define HD    64
#define BATCH 2
#define MTOT  (BATCH*S_LEN)   // 4096

// Scratch (device globals: allocation-free). Q/K/V kept in fp16 (Q pre-scaled).
__device__ __half g_q[BATCH*NH*S_LEN*HD];
__device__ __half g_k[BATCH*NH*S_LEN*HD];
__device__ __half g_v[BATCH*NH*S_LEN*HD];
__device__ float  g_attn[MTOT*EMB];

#define SSTRIDE 72   // padded smem row stride in halves (144 B)

// ---------------------------------------------------------------------------
// helpers
// ---------------------------------------------------------------------------
__device__ __forceinline__ uint32_t smem_u32(const void* p) {
    uint32_t a;
    asm("{ .reg .u64 t; cvta.to.shared.u64 t, %1; cvt.u32.u64 %0, t; }" : "=r"(a) : "l"(p));
    return a;
}
__device__ __forceinline__ uint32_t h2u(float a, float b) {
    __half2 h = __floats2half2_rn(a, b);
    return *(uint32_t*)&h;
}
__device__ __forceinline__ void ldsm4(uint32_t* r, uint32_t a) {
    asm volatile("ldmatrix.sync.aligned.m8n8.x4.shared.b16 {%0,%1,%2,%3}, [%4];"
        : "=r"(r[0]), "=r"(r[1]), "=r"(r[2]), "=r"(r[3]) : "r"(a));
}
__device__ __forceinline__ void ldsm4t(uint32_t* r, uint32_t a) {
    asm volatile("ldmatrix.sync.aligned.m8n8.x4.trans.shared.b16 {%0,%1,%2,%3}, [%4];"
        : "=r"(r[0]), "=r"(r[1]), "=r"(r[2]), "=r"(r[3]) : "r"(a));
}
__device__ __forceinline__ void mma16816(float* d, const uint32_t* a, uint32_t b0, uint32_t b1) {
    asm volatile(
        "mma.sync.aligned.m16n8k16.row.col.f32.f16.f16.f32 "
        "{%0,%1,%2,%3}, {%4,%5,%6,%7}, {%8,%9}, {%0,%1,%2,%3};"
        : "+f"(d[0]), "+f"(d[1]), "+f"(d[2]), "+f"(d[3])
        : "r"(a[0]), "r"(a[1]), "r"(a[2]), "r"(a[3]), "r"(b0), "r"(b1));
}

// ---------------------------------------------------------------------------
// HGEMM body: C = A @ W^T + bias.  A:[M,1024] f32 row-major, W:[N,1024] f32.
// CTA tile 128x128, 8 warps (4m x 2n), warp tile 32x64, K chunk 64.
// MODE 0: fp32 C[m*EMB+n].  MODE 1: fp16 scatter to [B,H,S,D] with scale.
// ---------------------------------------------------------------------------
template <int MODE>
__device__ __forceinline__
void hgemm_body(const float* __restrict__ A, const float* __restrict__ W,
                const float* __restrict__ bias, void* __restrict__ Cout, float oscale)
{
    __shared__ __half sA[128 * SSTRIDE];
    __shared__ __half sB[128 * SSTRIDE];

    const int tid = threadIdx.x;
    const int wid = tid >> 5, lane = tid & 31;
    const int wm = wid >> 1, wn = wid & 1;
    const int m0 = blockIdx.y * 128, n0 = blockIdx.x * 128;

    float acc[2][8][4];
    #pragma unroll
    for (int mt = 0; mt < 2; mt++)
        #pragma unroll
        for (int nt = 0; nt < 8; nt++)
            #pragma unroll
            for (int r = 0; r < 4; r++) acc[mt][nt][r] = 0.0f;

    const float* Ag = A + (size_t)m0 * EMB;
    const float* Bg = W + (size_t)n0 * EMB;
    const uint32_t sAu = smem_u32(sA), sBu = smem_u32(sB);

    for (int kc = 0; kc < EMB; kc += 64) {
        __syncthreads();
        #pragma unroll
        for (int i = 0; i < 8; i++) {
            int g = tid + 256 * i;
            int row = g >> 4, c4 = g & 15;
            float4 f = *(const float4*)(Ag + (size_t)row * EMB + kc + c4 * 4);
            *(uint2*)&sA[row * SSTRIDE + c4 * 4] = make_uint2(h2u(f.x, f.y), h2u(f.z, f.w));
        }
        #pragma unroll
        for (int i = 0; i < 8; i++) {
            int g = tid + 256 * i;
            int row = g >> 4, c4 = g & 15;
            float4 f = *(const float4*)(Bg + (size_t)row * EMB + kc + c4 * 4);
            *(uint2*)&sB[row * SSTRIDE + c4 * 4] = make_uint2(h2u(f.x, f.y), h2u(f.z, f.w));
        }
        __syncthreads();

        #pragma unroll
        for (int ks = 0; ks < 4; ks++) {
            uint32_t af[2][4];
            #pragma unroll
            for (int mt = 0; mt < 2; mt++) {
                int row = wm * 32 + mt * 16 + (lane & 15);
                ldsm4(af[mt], sAu + (uint32_t)(row * SSTRIDE + ks * 16 + ((lane >> 4) << 3)) * 2);
            }
            #pragma unroll
            for (int p = 0; p < 4; p++) {
                uint32_t bf[4];
                int row = wn * 64 + p * 16 + ((lane >> 4) << 3) + (lane & 7);
                int koff = ks * 16 + (((lane >> 3) & 1) << 3);
                ldsm4(bf, sBu + (uint32_t)(row * SSTRIDE + koff) * 2);
                #pragma unroll
                for (int mt = 0; mt < 2; mt++) {
                    mma16816(acc[mt][2 * p],     af[mt], bf[0], bf[1]);
                    mma16816(acc[mt][2 * p + 1], af[mt], bf[2], bf[3]);
                }
            }
        }
    }

    // epilogue
    #pragma unroll
    for (int mt = 0; mt < 2; mt++) {
        int rA = m0 + wm * 32 + mt * 16 + (lane >> 2);
        #pragma unroll
        for (int nt = 0; nt < 8; nt++) {
            int n = n0 + wn * 64 + nt * 8 + ((lane & 3) << 1);
            float b0 = bias[n], b1 = bias[n + 1];
            float v00 = acc[mt][nt][0] + b0, v01 = acc[mt][nt][1] + b1;
            float v10 = acc[mt][nt][2] + b0, v11 = acc[mt][nt][3] + b1;
            if (MODE == 0) {
                float* C = (float*)Cout;
                C[(size_t)rA * EMB + n]           = v00;
                C[(size_t)rA * EMB + n + 1]       = v01;
                C[(size_t)(rA + 8) * EMB + n]     = v10;
                C[(size_t)(rA + 8) * EMB + n + 1] = v11;
            } else {
                __half* C = (__half*)Cout;
                int h_ = n >> 6, d_ = n & 63;
                {
                    int b_ = rA >> 11, s_ = rA & 2047;
                    size_t base = (((size_t)(b_ * NH + h_) * S_LEN) + s_) * HD + d_;
                    C[base]     = __float2half(v00 * oscale);
                    C[base + 1] = __float2half(v01 * oscale);
                }
                {
                    int r2 = rA + 8;
                    int b_ = r2 >> 11, s_ = r2 & 2047;
                    size_t base = (((size_t)(b_ * NH + h_) * S_LEN) + s_) * HD + d_;
                    C[base]     = __float2half(v10 * oscale);
                    C[base + 1] = __float2half(v11 * oscale);
                }
            }
        }
    }
}

__global__ __launch_bounds__(256)
void qkv_gemm_kernel(const float* __restrict__ x,
                     const float* __restrict__ wq, const float* __restrict__ bq,
                     const float* __restrict__ wk, const float* __restrict__ bk,
                     const float* __restrict__ wv, const float* __restrict__ bv)
{
    if (blockIdx.z == 0)      hgemm_body<1>(x, wq, bq, g_q, 0.125f);
    else if (blockIdx.z == 1) hgemm_body<1>(x, wk, bk, g_k, 1.0f);
    else                      hgemm_body<1>(x, wv, bv, g_v, 1.0f);
}

__global__ __launch_bounds__(256)
void out_gemm_kernel(const float* __restrict__ wo, const float* __restrict__ bo,
                     float* __restrict__ out)
{
    hgemm_body<0>(g_attn, wo, bo, out, 1.0f);
}

// ---------------------------------------------------------------------------
// Flash attention with mma.sync. CTA: 128 Q rows, 8 warps x 16 rows, Bc=64.
// Q pre-scaled by 1/8 at projection. S = Q@K^T (row.col, both K-major),
// P@V via ldmatrix.trans on row-major V. Online softmax on fragments.
// ---------------------------------------------------------------------------
__global__ __launch_bounds__(256)
void flash_kernel()
{
    __shared__ __half Qs[128 * SSTRIDE];
    __shared__ __half Ks[64 * SSTRIDE];
    __shared__ __half Vs[64 * SSTRIDE];

    const int tid = threadIdx.x, wid = tid >> 5, lane = tid & 31;
    const int qt = blockIdx.x;          // 0..15 (128-row Q tiles)
    const int bh = blockIdx.y;          // 0..31

    const __half* Qg = g_q + ((size_t)bh * S_LEN + qt * 128) * HD;
    const __half* Kg = g_k + (size_t)bh * S_LEN * HD;
    const __half* Vg = g_v + (size_t)bh * S_LEN * HD;

    #pragma unroll
    for (int i = 0; i < 4; i++) {
        int g = tid + 256 * i;
        int row = g >> 3, u = g & 7;
        *(uint4*)&Qs[row * SSTRIDE + u * 8] = *(const uint4*)(Qg + (size_t)row * HD + u * 8);
    }

    float accO[8][4];
    #pragma unroll
    for (int dt = 0; dt < 8; dt++)
        #pragma unroll
        for (int r = 0; r < 4; r++) accO[dt][r] = 0.0f;
    float mA = -1e30f, mB = -1e30f, lA = 0.0f, lB = 0.0f;

    const int mrow = wid * 16;
    const uint32_t Qu = smem_u32(Qs), Ku = smem_u32(Ks), Vu = smem_u32(Vs);

    for (int kt = 0; kt < S_LEN / 64; kt++) {
        __syncthreads();
        const __half* Kp = Kg + (size_t)kt * 64 * HD;
        const __half* Vp = Vg + (size_t)kt * 64 * HD;
        #pragma unroll
        for (int i = 0; i < 2; i++) {
            int g = tid + 256 * i;
            int row = g >> 3, u = g & 7;
            *(uint4*)&Ks[row * SSTRIDE + u * 8] = *(const uint4*)(Kp + (size_t)row * HD + u * 8);
            *(uint4*)&Vs[row * SSTRIDE + u * 8] = *(const uint4*)(Vp + (size_t)row * HD + u * 8);
        }
        __syncthreads();

        // S = Q @ K^T  (scaled; Q carries 1/8)
        float sacc[8][4];
        #pragma unroll
        for (int nt = 0; nt < 8; nt++)
            #pragma unroll
            for (int r = 0; r < 4; r++) sacc[nt][r] = 0.0f;
        #pragma unroll
        for (int ks = 0; ks < 4; ks++) {
            uint32_t af[4];
            ldsm4(af, Qu + (uint32_t)((mrow + (lane & 15)) * SSTRIDE + ks * 16 + ((lane >> 4) << 3)) * 2);
            #pragma unroll
            for (int p = 0; p < 4; p++) {
                uint32_t bf[4];
                int row = p * 16 + ((lane >> 4) << 3) + (lane & 7);
                int koff = ks * 16 + (((lane >> 3) & 1) << 3);
                ldsm4(bf, Ku + (uint32_t)(row * SSTRIDE + koff) * 2);
                mma16816(sacc[2 * p],     af, bf[0], bf[1]);
                mma16816(sacc[2 * p + 1], af, bf[2], bf[3]);
            }
        }

        // online softmax (rows l/4 and l/4+8; cols spread over quad lanes)
        float mxA = -1e30f, mxB = -1e30f;
        #pragma unroll
        for (int nt = 0; nt < 8; nt++) {
            mxA = fmaxf(mxA, fmaxf(sacc[nt][0], sacc[nt][1]));
            mxB = fmaxf(mxB, fmaxf(sacc[nt][2], sacc[nt][3]));
        }
        mxA = fmaxf(mxA, __shfl_xor_sync(0xffffffffu, mxA, 1));
        mxA = fmaxf(mxA, __shfl_xor_sync(0xffffffffu, mxA, 2));
        mxB = fmaxf(mxB, __shfl_xor_sync(0xffffffffu, mxB, 1));
        mxB = fmaxf(mxB, __shfl_xor_sync(0xffffffffu, mxB, 2));
        float nmA = fmaxf(mA, mxA), nmB = fmaxf(mB, mxB);
        float scA = __expf(mA - nmA), scB = __expf(mB - nmB);
        mA = nmA; mB = nmB;
        float rsA = 0.0f, rsB = 0.0f;
        #pragma unroll
        for (int nt = 0; nt < 8; nt++) {
            sacc[nt][0] = __expf(sacc[nt][0] - nmA);
            sacc[nt][1] = __expf(sacc[nt][1] - nmA);
            sacc[nt][2] = __expf(sacc[nt][2] - nmB);
            sacc[nt][3] = __expf(sacc[nt][3] - nmB);
            rsA += sacc[nt][0] + sacc[nt][1];
            rsB += sacc[nt][2] + sacc[nt][3];
        }
        rsA += __shfl_xor_sync(0xffffffffu, rsA, 1);
        rsA += __shfl_xor_sync(0xffffffffu, rsA, 2);
        rsB += __shfl_xor_sync(0xffffffffu, rsB, 1);
        rsB += __shfl_xor_sync(0xffffffffu, rsB, 2);
        lA = lA * scA + rsA;
        lB = lB * scB + rsB;
        #pragma unroll
        for (int dt = 0; dt < 8; dt++) {
            accO[dt][0] *= scA; accO[dt][1] *= scA;
            accO[dt][2] *= scB; accO[dt][3] *= scB;
        }

        // O += P @ V   (P fragment == S fragment layout; V via ldmatrix.trans)
        #pragma unroll
        for (int ks = 0; ks < 4; ks++) {
            uint32_t pf[4];
            pf[0] = h2u(sacc[2 * ks][0],     sacc[2 * ks][1]);
            pf[1] = h2u(sacc[2 * ks][2],     sacc[2 * ks][3]);
            pf[2] = h2u(sacc[2 * ks + 1][0], sacc[2 * ks + 1][1]);
            pf[3] = h2u(sacc[2 * ks + 1][2], sacc[2 * ks + 1][3]);
            #pragma unroll
            for (int p = 0; p < 4; p++) {
                uint32_t bf[4];
                int row = ks * 16 + (((lane >> 3) & 1) << 3) + (lane & 7);
                int col = p * 16 + ((lane >> 4) << 3);
                ldsm4t(bf, Vu + (uint32_t)(row * SSTRIDE + col) * 2);
                mma16816(accO[2 * p],     pf, bf[0], bf[1]);
                mma16816(accO[2 * p + 1], pf, bf[2], bf[3]);
            }
        }
    }

    // normalize + write [B,S,E] fp32
    float invA = 1.0f / lA, invB = 1.0f / lB;
    const int b_ = bh >> 4, h_ = bh & 15;
    const int rowA = qt * 128 + mrow + (lane >> 2);
    #pragma unroll
    for (int dt = 0; dt < 8; dt++) {
        int d = dt * 8 + ((lane & 3) << 1);
        float* o0 = &g_attn[((size_t)(b_ * S_LEN + rowA)) * EMB + h_ * HD + d];
        o0[0] = accO[dt][0] * invA;
        o0[1] = accO[dt][1] * invA;
        float* o1 = &g_attn[((size_t)(b_ * S_LEN + rowA + 8)) * EMB + h_ * HD + d];
        o1[0] = accO[dt][2] * invB;
        o1[1] = accO[dt][3] * invB;
    }
}

extern "C" void kernel_launch(void* const* d_in, const int* in_sizes, int n_in,
                              void* d_out, int out_size)
{
    const float* x  = (const float*)d_in[0];
    const float* wq = (const float*)d_in[1];
    const float* bq = (const float*)d_in[2];
    const float* wk = (const float*)d_in[3];
    const float* bk = (const float*)d_in[4];
    const float* wv = (const float*)d_in[5];
    const float* bv = (const float*)d_in[6];
    const float* wo = (const float*)d_in[7];
    const float* bo = (const float*)d_in[8];
    float* out = (float*)d_out;

    dim3 gq(EMB / 128, MTOT / 128, 3);   // 8 x 32 x 3
    qkv_gemm_kernel<<<gq, 256>>>(x, wq, bq, wk, bk, wv, bv);

    flash_kernel<<<dim3(S_LEN / 128, BATCH * NH), 256>>>();   // 16 x 32

    dim3 gg(EMB / 128, MTOT / 128);      // 8 x 32
    out_gemm_kernel<<<gg, 256>>>(wo, bo, out);
}